// round 1
// baseline (speedup 1.0000x reference)
#include <cuda_runtime.h>
#include <cuda_bf16.h>
#include <math.h>

// Problem constants
#define BATCH   8
#define SEQ     1024
#define HID     768
#define NHEADS  12
#define HDIM    64
#define QKV_N   (3*HID)          // 2304
#define MTOT    (BATCH*SEQ)      // 8192

// Scratch (allocation-free: __device__ globals)
__device__ float g_qkv[(size_t)MTOT * QKV_N];   // [B*S, 2304]
__device__ float g_o[(size_t)MTOT * HID];       // [B*S, 768]

// ---------------------------------------------------------------------------
// SGEMM with fused affine epilogue:  C = (A@B + bias?) * scale + shift
// A [M,K] row-major, B [K,N] row-major, C [M,N].
// 64x64 block tile, 16 K-tile, 256 threads, 4x4 per thread.
// M%64==0, N%64==0, K%16==0 assumed (true for all our shapes).
// ---------------------------------------------------------------------------
__global__ __launch_bounds__(256)
void sgemm_affine(const float* __restrict__ A, const float* __restrict__ B,
                  float* __restrict__ C, int M, int N, int K,
                  const float* __restrict__ bias,
                  const float* __restrict__ scale,
                  const float* __restrict__ shift)
{
    __shared__ float As[16][64];   // [k][m]  (A transposed)
    __shared__ float Bs[16][64];   // [k][n]

    const int tid = threadIdx.x;
    const int tx = tid & 15;       // n sub-tile
    const int ty = tid >> 4;       // m sub-tile
    const int n0 = blockIdx.x * 64;
    const int m0 = blockIdx.y * 64;

    float acc[4][4];
#pragma unroll
    for (int a = 0; a < 4; a++)
#pragma unroll
        for (int b = 0; b < 4; b++) acc[a][b] = 0.f;

    // load indices
    const int am = tid >> 2;            // 0..63 row of A tile
    const int ak = (tid & 3) * 4;       // 0..12 k offset (float4)
    const int bk = tid >> 4;            // 0..15 row of B tile
    const int bn = tid & 15;            // float4 col index

    for (int k0 = 0; k0 < K; k0 += 16) {
        float4 av = *(const float4*)(A + (size_t)(m0 + am) * K + k0 + ak);
        float4 bv = *(const float4*)(B + (size_t)(k0 + bk) * N + n0 + bn * 4);
        As[ak + 0][am] = av.x;
        As[ak + 1][am] = av.y;
        As[ak + 2][am] = av.z;
        As[ak + 3][am] = av.w;
        ((float4*)(&Bs[bk][0]))[bn] = bv;
        __syncthreads();

#pragma unroll
        for (int kk = 0; kk < 16; kk++) {
            float a_f[4];
#pragma unroll
            for (int a = 0; a < 4; a++) a_f[a] = As[kk][ty * 4 + a];
            float4 b4 = ((float4*)(&Bs[kk][0]))[tx];
            float b_f[4] = {b4.x, b4.y, b4.z, b4.w};
#pragma unroll
            for (int a = 0; a < 4; a++)
#pragma unroll
                for (int b = 0; b < 4; b++) acc[a][b] = fmaf(a_f[a], b_f[b], acc[a][b]);
        }
        __syncthreads();
    }

    // epilogue
    const int nc = n0 + tx * 4;
    float4 sc4 = *(const float4*)(scale + nc);
    float4 sh4 = *(const float4*)(shift + nc);
    float bi[4] = {0.f, 0.f, 0.f, 0.f};
    if (bias) {
        float4 b4 = *(const float4*)(bias + nc);
        bi[0] = b4.x; bi[1] = b4.y; bi[2] = b4.z; bi[3] = b4.w;
    }
    float scv[4] = {sc4.x, sc4.y, sc4.z, sc4.w};
    float shv[4] = {sh4.x, sh4.y, sh4.z, sh4.w};
#pragma unroll
    for (int a = 0; a < 4; a++) {
        float4 r;
        r.x = (acc[a][0] + bi[0]) * scv[0] + shv[0];
        r.y = (acc[a][1] + bi[1]) * scv[1] + shv[1];
        r.z = (acc[a][2] + bi[2]) * scv[2] + shv[2];
        r.w = (acc[a][3] + bi[3]) * scv[3] + shv[3];
        *(float4*)(C + (size_t)(m0 + ty * 4 + a) * N + nc) = r;
    }
}

// ---------------------------------------------------------------------------
// Flash-attention fp32.
// grid: (SEQ/64, BATCH*NHEADS), block 256 (16x16 logical, 4x4 per thread).
// qkv layout: [(b*S+s)*2304 + which*768 + h*64 + d]
// out layout: [(b*S+s)*768 + h*64 + d]
// Shared: Qs[64][64] row-major, KPs[64][64] (K transposed d-major with
// column rotation (j+d)&63, later reused as P[i][j]), Vs[64][64] row-major.
// Exactly 48KB static smem.
// ---------------------------------------------------------------------------
__global__ __launch_bounds__(256)
void attn_flash(const float* __restrict__ qkv, float* __restrict__ out)
{
    __shared__ float Qs[64][64];
    __shared__ float KPs[64][64];
    __shared__ float Vs[64][64];

    const int tid = threadIdx.x;
    const int tx = tid & 15;
    const int ty = tid >> 4;
    const int s0 = blockIdx.x * 64;
    const int bh = blockIdx.y;
    const int b = bh / NHEADS;
    const int h = bh - b * NHEADS;

    const float* qbase = qkv + (size_t)b * SEQ * QKV_N + h * HDIM;
    const float* kbase = qbase + HID;
    const float* vbase = qbase + 2 * HID;

    // Load Q tile (rows s0..s0+63) coalesced, row-major.
    {
        int row = tid >> 4;            // 0..15 step below
#pragma unroll
        for (int it = 0; it < 4; it++) {
            int i = tid + it * 256;    // i over 1024 float4 units (64 rows x 16)
            int r = i >> 4, c4 = i & 15;
            float4 v = *(const float4*)(qbase + (size_t)(s0 + r) * QKV_N + c4 * 4);
            ((float4*)(&Qs[r][0]))[c4] = v;
        }
        (void)row;
    }

    float m[4], l[4], o_acc[4][4];
#pragma unroll
    for (int a = 0; a < 4; a++) {
        m[a] = -1e30f; l[a] = 0.f;
#pragma unroll
        for (int bb = 0; bb < 4; bb++) o_acc[a][bb] = 0.f;
    }

    const float sm_scale = 0.125f;  // 1/sqrt(64)

    for (int t = 0; t < SEQ / 64; t++) {
        const int j0 = t * 64;
        __syncthreads();   // previous iteration's P/V reads complete
        // Load K (transposed+rotated) and V tiles
#pragma unroll
        for (int it = 0; it < 4; it++) {
            int i = tid + it * 256;
            int j = i >> 4;
            int d0 = (i & 15) * 4;
            float4 kv = *(const float4*)(kbase + (size_t)(j0 + j) * QKV_N + d0);
            KPs[d0 + 0][(j + d0 + 0) & 63] = kv.x;
            KPs[d0 + 1][(j + d0 + 1) & 63] = kv.y;
            KPs[d0 + 2][(j + d0 + 2) & 63] = kv.z;
            KPs[d0 + 3][(j + d0 + 3) & 63] = kv.w;
            float4 vv = *(const float4*)(vbase + (size_t)(j0 + j) * QKV_N + d0);
            ((float4*)(&Vs[j][0]))[i & 15] = vv;
        }
        __syncthreads();

        // S = Q K^T * scale  (4x4 per thread)
        float s_acc[4][4];
#pragma unroll
        for (int a = 0; a < 4; a++)
#pragma unroll
            for (int bb = 0; bb < 4; bb++) s_acc[a][bb] = 0.f;

#pragma unroll 8
        for (int dd = 0; dd < 64; dd++) {
            float q_f[4], k_f[4];
#pragma unroll
            for (int a = 0; a < 4; a++) q_f[a] = Qs[ty * 4 + a][dd];
#pragma unroll
            for (int bb = 0; bb < 4; bb++) k_f[bb] = KPs[dd][(tx * 4 + bb + dd) & 63];
#pragma unroll
            for (int a = 0; a < 4; a++)
#pragma unroll
                for (int bb = 0; bb < 4; bb++)
                    s_acc[a][bb] = fmaf(q_f[a], k_f[bb], s_acc[a][bb]);
        }

        // online softmax (row reductions across the 16-lane tx group)
#pragma unroll
        for (int a = 0; a < 4; a++) {
            float rmax = -1e30f;
#pragma unroll
            for (int bb = 0; bb < 4; bb++) {
                s_acc[a][bb] *= sm_scale;
                rmax = fmaxf(rmax, s_acc[a][bb]);
            }
#pragma unroll
            for (int off = 8; off >= 1; off >>= 1)
                rmax = fmaxf(rmax, __shfl_xor_sync(0xffffffffu, rmax, off));
            float newm = fmaxf(m[a], rmax);
            float rsum = 0.f;
#pragma unroll
            for (int bb = 0; bb < 4; bb++) {
                float p = __expf(s_acc[a][bb] - newm);
                s_acc[a][bb] = p;   // reuse as P
                rsum += p;
            }
#pragma unroll
            for (int off = 8; off >= 1; off >>= 1)
                rsum += __shfl_xor_sync(0xffffffffu, rsum, off);
            float corr = __expf(m[a] - newm);
            l[a] = l[a] * corr + rsum;
            m[a] = newm;
#pragma unroll
            for (int bb = 0; bb < 4; bb++) o_acc[a][bb] *= corr;
        }

        __syncthreads();   // everyone done reading KPs as K
        // write P
#pragma unroll
        for (int a = 0; a < 4; a++)
#pragma unroll
            for (int bb = 0; bb < 4; bb++)
                KPs[ty * 4 + a][tx * 4 + bb] = s_acc[a][bb];
        __syncthreads();

        // O += P @ V
#pragma unroll 8
        for (int kk = 0; kk < 64; kk++) {
            float p_f[4];
#pragma unroll
            for (int a = 0; a < 4; a++) p_f[a] = KPs[ty * 4 + a][kk];
            float4 v4 = ((float4*)(&Vs[kk][0]))[tx];
#pragma unroll
            for (int a = 0; a < 4; a++) {
                o_acc[a][0] = fmaf(p_f[a], v4.x, o_acc[a][0]);
                o_acc[a][1] = fmaf(p_f[a], v4.y, o_acc[a][1]);
                o_acc[a][2] = fmaf(p_f[a], v4.z, o_acc[a][2]);
                o_acc[a][3] = fmaf(p_f[a], v4.w, o_acc[a][3]);
            }
        }
    }

    // write output
#pragma unroll
    for (int a = 0; a < 4; a++) {
        float inv = 1.0f / l[a];
        float4 r;
        r.x = o_acc[a][0] * inv;
        r.y = o_acc[a][1] * inv;
        r.z = o_acc[a][2] * inv;
        r.w = o_acc[a][3] * inv;
        *(float4*)(out + (size_t)(b * SEQ + s0 + ty * 4 + a) * HID + h * HDIM + tx * 4) = r;
    }
}

// ---------------------------------------------------------------------------
// Launch
// ---------------------------------------------------------------------------
extern "C" void kernel_launch(void* const* d_in, const int* in_sizes, int n_in,
                              void* d_out, int out_size)
{
    (void)in_sizes; (void)n_in; (void)out_size;
    const float* x      = (const float*)d_in[0];   // [8,1024,768]
    const float* Wqkv   = (const float*)d_in[1];   // [768,2304]
    const float* scale1 = (const float*)d_in[2];   // [2304]
    const float* shift1 = (const float*)d_in[3];   // [2304]
    const float* Wout   = (const float*)d_in[4];   // [768,768]
    const float* bout   = (const float*)d_in[5];   // [768]
    const float* scale2 = (const float*)d_in[6];   // [768]
    const float* shift2 = (const float*)d_in[7];   // [768]
    float* out = (float*)d_out;

    float* qkv_buf = nullptr;
    float* o_buf = nullptr;
    cudaGetSymbolAddress((void**)&qkv_buf, g_qkv);
    cudaGetSymbolAddress((void**)&o_buf, g_o);

    // 1) QKV projection + SSF affine
    {
        dim3 grid(QKV_N / 64, MTOT / 64);
        sgemm_affine<<<grid, 256>>>(x, Wqkv, qkv_buf, MTOT, QKV_N, HID,
                                    nullptr, scale1, shift1);
    }
    // 2) attention
    {
        dim3 grid(SEQ / 64, BATCH * NHEADS);
        attn_flash<<<grid, 256>>>(qkv_buf, o_buf);
    }
    // 3) out projection + bias + SSF affine
    {
        dim3 grid(HID / 64, MTOT / 64);
        sgemm_affine<<<grid, 256>>>(o_buf, Wout, out, MTOT, HID, HID,
                                    bout, scale2, shift2);
    }
}

// round 2
// speedup vs baseline: 3.2554x; 3.2554x over previous
#include <cuda_runtime.h>
#include <cuda_bf16.h>
#include <math.h>
#include <stdint.h>

#define BATCH   8
#define SEQ     1024
#define HID     768
#define NHEADS  12
#define HDIM    64
#define QKV_N   (3*HID)          // 2304
#define MTOT    (BATCH*SEQ)      // 8192

__device__ float g_qkv[(size_t)MTOT * QKV_N];   // [B*S, 2304]
__device__ float g_o[(size_t)MTOT * HID];       // [B*S, 768]

__device__ __forceinline__ uint32_t f2tf32(float f) {
    uint32_t r;
    asm("cvt.rna.tf32.f32 %0, %1;" : "=r"(r) : "f"(f));
    return r;
}

__device__ __forceinline__ void mma_tf32(float* c,
                                         uint32_t a0, uint32_t a1, uint32_t a2, uint32_t a3,
                                         uint32_t b0, uint32_t b1) {
    asm volatile(
        "mma.sync.aligned.m16n8k8.row.col.f32.tf32.tf32.f32 "
        "{%0,%1,%2,%3}, {%4,%5,%6,%7}, {%8,%9}, {%0,%1,%2,%3};"
        : "+f"(c[0]), "+f"(c[1]), "+f"(c[2]), "+f"(c[3])
        : "r"(a0), "r"(a1), "r"(a2), "r"(a3), "r"(b0), "r"(b1));
}

__device__ __forceinline__ uint4 cvt4(float4 v) {
    uint4 r;
    r.x = f2tf32(v.x); r.y = f2tf32(v.y); r.z = f2tf32(v.z); r.w = f2tf32(v.w);
    return r;
}

// ---------------------------------------------------------------------------
// tf32 GEMM with fused affine epilogue: C = (A@B + bias?) * scale + shift
// A [M,K] row-major fp32, B [K,N] row-major fp32, C [M,N] fp32.
// Block tile 128x128, K-tile 16. 8 warps in 2x4 grid, warp tile 64x32.
// Requires M%128==0, N%128==0, K%16==0.
// ---------------------------------------------------------------------------
#define AS_STRIDE 20    // 128 rows x 16 cols, row stride 20 (frag loads conflict-free)
#define BS_STRIDE 136   // 16 rows x 128 cols, row stride 136

__global__ __launch_bounds__(256)
void gemm_tf32(const float* __restrict__ A, const float* __restrict__ B,
               float* __restrict__ C, int M, int N, int K,
               const float* __restrict__ bias,
               const float* __restrict__ scale,
               const float* __restrict__ shift)
{
    __shared__ uint32_t As[128 * AS_STRIDE];   // A tile, row-major [m][k]
    __shared__ uint32_t Bs[16 * BS_STRIDE];    // B tile, row-major [k][n]

    const int tid  = threadIdx.x;
    const int lane = tid & 31;
    const int warp = tid >> 5;
    const int g = lane >> 2;     // 0..7
    const int q = lane & 3;      // 0..3
    const int wm0 = (warp >> 2) * 64;   // warp m offset in tile
    const int wn0 = (warp & 3) * 32;    // warp n offset in tile
    const int m0 = blockIdx.y * 128;
    const int n0 = blockIdx.x * 128;

    float acc[4][4][4];   // [mf][nf][c]
#pragma unroll
    for (int mf = 0; mf < 4; mf++)
#pragma unroll
        for (int nf = 0; nf < 4; nf++)
#pragma unroll
            for (int cc = 0; cc < 4; cc++) acc[mf][nf][cc] = 0.f;

    for (int k0 = 0; k0 < K; k0 += 16) {
        // load A tile: 128x16 = 512 float4 units, 2 per thread
#pragma unroll
        for (int it = 0; it < 2; it++) {
            int u = tid + it * 256;
            int r = u >> 2, c4 = u & 3;
            float4 v = *(const float4*)(A + (size_t)(m0 + r) * K + k0 + c4 * 4);
            *(uint4*)(&As[r * AS_STRIDE + c4 * 4]) = cvt4(v);
        }
        // load B tile: 16x128 = 512 float4 units
#pragma unroll
        for (int it = 0; it < 2; it++) {
            int u = tid + it * 256;
            int r = u >> 5, c4 = u & 31;
            float4 v = *(const float4*)(B + (size_t)(k0 + r) * N + n0 + c4 * 4);
            *(uint4*)(&Bs[r * BS_STRIDE + c4 * 4]) = cvt4(v);
        }
        __syncthreads();

#pragma unroll
        for (int ks = 0; ks < 2; ks++) {
            uint32_t af[4][4], bf[4][2];
#pragma unroll
            for (int mf = 0; mf < 4; mf++) {
                int r = wm0 + mf * 16 + g;
                int c = ks * 8 + q;
                af[mf][0] = As[r * AS_STRIDE + c];
                af[mf][1] = As[(r + 8) * AS_STRIDE + c];
                af[mf][2] = As[r * AS_STRIDE + c + 4];
                af[mf][3] = As[(r + 8) * AS_STRIDE + c + 4];
            }
#pragma unroll
            for (int nf = 0; nf < 4; nf++) {
                int n = wn0 + nf * 8 + g;
                int k = ks * 8 + q;
                bf[nf][0] = Bs[k * BS_STRIDE + n];
                bf[nf][1] = Bs[(k + 4) * BS_STRIDE + n];
            }
#pragma unroll
            for (int mf = 0; mf < 4; mf++)
#pragma unroll
                for (int nf = 0; nf < 4; nf++)
                    mma_tf32(acc[mf][nf], af[mf][0], af[mf][1], af[mf][2], af[mf][3],
                             bf[nf][0], bf[nf][1]);
        }
        __syncthreads();
    }

    // epilogue: (acc + bias) * scale + shift
#pragma unroll
    for (int nf = 0; nf < 4; nf++) {
        int c = n0 + wn0 + nf * 8 + 2 * q;
        float2 sc = *(const float2*)(scale + c);
        float2 sh = *(const float2*)(shift + c);
        float2 bi = make_float2(0.f, 0.f);
        if (bias) bi = *(const float2*)(bias + c);
#pragma unroll
        for (int mf = 0; mf < 4; mf++) {
            int r = m0 + wm0 + mf * 16 + g;
            float2 lo, hi;
            lo.x = (acc[mf][nf][0] + bi.x) * sc.x + sh.x;
            lo.y = (acc[mf][nf][1] + bi.y) * sc.y + sh.y;
            hi.x = (acc[mf][nf][2] + bi.x) * sc.x + sh.x;
            hi.y = (acc[mf][nf][3] + bi.y) * sc.y + sh.y;
            *(float2*)(C + (size_t)r * N + c) = lo;
            *(float2*)(C + (size_t)(r + 8) * N + c) = hi;
        }
    }
}

// ---------------------------------------------------------------------------
// tf32 flash attention. grid (SEQ/64, BATCH*NHEADS), 128 threads (4 warps).
// Each warp owns 16 query rows. K,V tiles of 64 rows.
// qkv layout: [(b*S+s)*2304 + which*768 + h*64 + d]
// ---------------------------------------------------------------------------
#define KS_STRIDE 68
#define VS_STRIDE 72

__global__ __launch_bounds__(128)
void attn_tf32(const float* __restrict__ qkv, float* __restrict__ out)
{
    __shared__ uint32_t Ks[64 * KS_STRIDE];   // K tile row-major [j][d]; Q staged here first
    __shared__ uint32_t Vs[64 * VS_STRIDE];   // V tile row-major [j][d]

    const int tid  = threadIdx.x;
    const int lane = tid & 31;
    const int warp = tid >> 5;     // 0..3
    const int g = lane >> 2;
    const int q = lane & 3;
    const int s0 = blockIdx.x * 64;
    const int bh = blockIdx.y;
    const int b = bh / NHEADS;
    const int h = bh - b * NHEADS;

    const float* qbase = qkv + (size_t)b * SEQ * QKV_N + h * HDIM;
    const float* kbase = qbase + HID;
    const float* vbase = qbase + 2 * HID;

    // Stage Q tile into Ks region, extract A-fragments (fixed for whole kernel)
#pragma unroll
    for (int it = 0; it < 8; it++) {
        int u = tid + it * 128;
        int r = u >> 4, c4 = u & 15;
        float4 v = *(const float4*)(qbase + (size_t)(s0 + r) * QKV_N + c4 * 4);
        *(uint4*)(&Ks[r * KS_STRIDE + c4 * 4]) = cvt4(v);
    }
    __syncthreads();

    uint32_t qa[8][4];
    {
        int r = warp * 16 + g;
#pragma unroll
        for (int ks = 0; ks < 8; ks++) {
            int c = ks * 8 + q;
            qa[ks][0] = Ks[r * KS_STRIDE + c];
            qa[ks][1] = Ks[(r + 8) * KS_STRIDE + c];
            qa[ks][2] = Ks[r * KS_STRIDE + c + 4];
            qa[ks][3] = Ks[(r + 8) * KS_STRIDE + c + 4];
        }
    }
    __syncthreads();

    float o_acc[8][4];
#pragma unroll
    for (int nf = 0; nf < 8; nf++)
#pragma unroll
        for (int cc = 0; cc < 4; cc++) o_acc[nf][cc] = 0.f;
    float m0r = -1e30f, m1r = -1e30f, l0r = 0.f, l1r = 0.f;
    const float sm_scale = 0.125f;

    const int src0 = (lane & ~3) | (q >> 1);
    const int src2 = (lane & ~3) | ((q >> 1) + 2);
    const int sel = q & 1;

    for (int t = 0; t < SEQ / 64; t++) {
        const int j0 = t * 64;
        // load K and V tiles (row-major, tf32-rounded)
#pragma unroll
        for (int it = 0; it < 8; it++) {
            int u = tid + it * 128;
            int r = u >> 4, c4 = u & 15;
            float4 kv = *(const float4*)(kbase + (size_t)(j0 + r) * QKV_N + c4 * 4);
            *(uint4*)(&Ks[r * KS_STRIDE + c4 * 4]) = cvt4(kv);
            float4 vv = *(const float4*)(vbase + (size_t)(j0 + r) * QKV_N + c4 * 4);
            *(uint4*)(&Vs[r * VS_STRIDE + c4 * 4]) = cvt4(vv);
        }
        __syncthreads();

        // S = Q K^T
        float s[8][4];
#pragma unroll
        for (int nf = 0; nf < 8; nf++)
#pragma unroll
            for (int cc = 0; cc < 4; cc++) s[nf][cc] = 0.f;

#pragma unroll
        for (int ks = 0; ks < 8; ks++) {
#pragma unroll
            for (int nf = 0; nf < 8; nf++) {
                uint32_t b0 = Ks[(nf * 8 + g) * KS_STRIDE + ks * 8 + q];
                uint32_t b1 = Ks[(nf * 8 + g) * KS_STRIDE + ks * 8 + q + 4];
                mma_tf32(s[nf], qa[ks][0], qa[ks][1], qa[ks][2], qa[ks][3], b0, b1);
            }
        }

        // online softmax; rows r=warp*16+g (c0,c1) and r+8 (c2,c3)
        float mx0 = -1e30f, mx1 = -1e30f;
#pragma unroll
        for (int nf = 0; nf < 8; nf++) {
#pragma unroll
            for (int cc = 0; cc < 4; cc++) s[nf][cc] *= sm_scale;
            mx0 = fmaxf(mx0, fmaxf(s[nf][0], s[nf][1]));
            mx1 = fmaxf(mx1, fmaxf(s[nf][2], s[nf][3]));
        }
        mx0 = fmaxf(mx0, __shfl_xor_sync(0xffffffffu, mx0, 1));
        mx0 = fmaxf(mx0, __shfl_xor_sync(0xffffffffu, mx0, 2));
        mx1 = fmaxf(mx1, __shfl_xor_sync(0xffffffffu, mx1, 1));
        mx1 = fmaxf(mx1, __shfl_xor_sync(0xffffffffu, mx1, 2));
        float nm0 = fmaxf(m0r, mx0);
        float nm1 = fmaxf(m1r, mx1);
        float sum0 = 0.f, sum1 = 0.f;
#pragma unroll
        for (int nf = 0; nf < 8; nf++) {
            s[nf][0] = __expf(s[nf][0] - nm0);
            s[nf][1] = __expf(s[nf][1] - nm0);
            s[nf][2] = __expf(s[nf][2] - nm1);
            s[nf][3] = __expf(s[nf][3] - nm1);
            sum0 += s[nf][0] + s[nf][1];
            sum1 += s[nf][2] + s[nf][3];
        }
        sum0 += __shfl_xor_sync(0xffffffffu, sum0, 1);
        sum0 += __shfl_xor_sync(0xffffffffu, sum0, 2);
        sum1 += __shfl_xor_sync(0xffffffffu, sum1, 1);
        sum1 += __shfl_xor_sync(0xffffffffu, sum1, 2);
        float corr0 = __expf(m0r - nm0);
        float corr1 = __expf(m1r - nm1);
        l0r = l0r * corr0 + sum0;
        l1r = l1r * corr1 + sum1;
        m0r = nm0; m1r = nm1;
#pragma unroll
        for (int nf = 0; nf < 8; nf++) {
            o_acc[nf][0] *= corr0; o_acc[nf][1] *= corr0;
            o_acc[nf][2] *= corr1; o_acc[nf][3] *= corr1;
        }

        // P (C-layout) -> A-layout via shuffles, then O += P @ V
#pragma unroll
        for (int ks = 0; ks < 8; ks++) {
            float v00 = __shfl_sync(0xffffffffu, s[ks][0], src0);
            float v01 = __shfl_sync(0xffffffffu, s[ks][1], src0);
            float v20 = __shfl_sync(0xffffffffu, s[ks][0], src2);
            float v21 = __shfl_sync(0xffffffffu, s[ks][1], src2);
            float v10 = __shfl_sync(0xffffffffu, s[ks][2], src0);
            float v11 = __shfl_sync(0xffffffffu, s[ks][3], src0);
            float v30 = __shfl_sync(0xffffffffu, s[ks][2], src2);
            float v31 = __shfl_sync(0xffffffffu, s[ks][3], src2);
            uint32_t pa0 = f2tf32(sel ? v01 : v00);
            uint32_t pa1 = f2tf32(sel ? v11 : v10);
            uint32_t pa2 = f2tf32(sel ? v21 : v20);
            uint32_t pa3 = f2tf32(sel ? v31 : v30);
#pragma unroll
            for (int nf = 0; nf < 8; nf++) {
                uint32_t b0 = Vs[(ks * 8 + q) * VS_STRIDE + nf * 8 + g];
                uint32_t b1 = Vs[(ks * 8 + q + 4) * VS_STRIDE + nf * 8 + g];
                mma_tf32(o_acc[nf], pa0, pa1, pa2, pa3, b0, b1);
            }
        }
        __syncthreads();
    }

    // normalize and write
    float inv0 = 1.0f / l0r;
    float inv1 = 1.0f / l1r;
    int r0 = b * SEQ + s0 + warp * 16 + g;
#pragma unroll
    for (int nf = 0; nf < 8; nf++) {
        int c = h * HDIM + nf * 8 + 2 * q;
        float2 lo, hi;
        lo.x = o_acc[nf][0] * inv0; lo.y = o_acc[nf][1] * inv0;
        hi.x = o_acc[nf][2] * inv1; hi.y = o_acc[nf][3] * inv1;
        *(float2*)(out + (size_t)r0 * HID + c) = lo;
        *(float2*)(out + (size_t)(r0 + 8) * HID + c) = hi;
    }
}

// ---------------------------------------------------------------------------
extern "C" void kernel_launch(void* const* d_in, const int* in_sizes, int n_in,
                              void* d_out, int out_size)
{
    (void)in_sizes; (void)n_in; (void)out_size;
    const float* x      = (const float*)d_in[0];
    const float* Wqkv   = (const float*)d_in[1];
    const float* scale1 = (const float*)d_in[2];
    const float* shift1 = (const float*)d_in[3];
    const float* Wout   = (const float*)d_in[4];
    const float* bout   = (const float*)d_in[5];
    const float* scale2 = (const float*)d_in[6];
    const float* shift2 = (const float*)d_in[7];
    float* out = (float*)d_out;

    float* qkv_buf = nullptr;
    float* o_buf = nullptr;
    cudaGetSymbolAddress((void**)&qkv_buf, g_qkv);
    cudaGetSymbolAddress((void**)&o_buf, g_o);

    {   // 1) QKV projection + SSF affine
        dim3 grid(QKV_N / 128, MTOT / 128);
        gemm_tf32<<<grid, 256>>>(x, Wqkv, qkv_buf, MTOT, QKV_N, HID,
                                 nullptr, scale1, shift1);
    }
    {   // 2) attention
        dim3 grid(SEQ / 64, BATCH * NHEADS);
        attn_tf32<<<grid, 128>>>(qkv_buf, o_buf);
    }
    {   // 3) out projection + bias + SSF affine
        dim3 grid(HID / 128, MTOT / 128);
        gemm_tf32<<<grid, 256>>>(o_buf, Wout, out, MTOT, HID, HID,
                                 bout, scale2, shift2);
    }
}

// round 4
// speedup vs baseline: 4.3707x; 1.3426x over previous
#include <cuda_runtime.h>
#include <cuda_bf16.h>
#include <math.h>
#include <stdint.h>

#define BATCH   8
#define SEQ     1024
#define HID     768
#define NHEADS  12
#define HDIM    64
#define QKV_N   (3*HID)          // 2304
#define MTOT    (BATCH*SEQ)      // 8192

__device__ float g_qkv[(size_t)MTOT * QKV_N];    // [B*S, 2304]
__device__ float g_o[(size_t)MTOT * HID];        // [B*S, 768]
__device__ float g_wt_qkv[(size_t)QKV_N * HID];  // Wqkv^T [2304, 768]
__device__ float g_wt_out[(size_t)HID * HID];    // Wout^T [768, 768]

// ---------------------------------------------------------------------------
// helpers
// ---------------------------------------------------------------------------
__device__ __forceinline__ uint32_t smem_u32(const void* p) {
    uint32_t a;
    asm("{ .reg .u64 t; cvta.to.shared.u64 t, %1; cvt.u32.u64 %0, t; }" : "=r"(a) : "l"(p));
    return a;
}
__device__ __forceinline__ uint32_t f2tf32(float f) {
    uint32_t r;
    asm("cvt.rna.tf32.f32 %0, %1;" : "=r"(r) : "f"(f));
    return r;
}
__device__ __forceinline__ uint4 cvt4(float4 v) {
    uint4 r;
    r.x = f2tf32(v.x); r.y = f2tf32(v.y); r.z = f2tf32(v.z); r.w = f2tf32(v.w);
    return r;
}
__device__ __forceinline__ void mma_tf32(float* c,
                                         uint32_t a0, uint32_t a1, uint32_t a2, uint32_t a3,
                                         uint32_t b0, uint32_t b1) {
    asm volatile(
        "mma.sync.aligned.m16n8k8.row.col.f32.tf32.tf32.f32 "
        "{%0,%1,%2,%3}, {%4,%5,%6,%7}, {%8,%9}, {%0,%1,%2,%3};"
        : "+f"(c[0]), "+f"(c[1]), "+f"(c[2]), "+f"(c[3])
        : "r"(a0), "r"(a1), "r"(a2), "r"(a3), "r"(b0), "r"(b1));
}
#define LDSM_X4(r0, r1, r2, r3, addr) \
    asm volatile("ldmatrix.sync.aligned.m8n8.x4.shared.b16 {%0,%1,%2,%3}, [%4];" \
        : "=r"(r0), "=r"(r1), "=r"(r2), "=r"(r3) : "r"(addr))
__device__ __forceinline__ void cp16(uint32_t dst, const void* src) {
    asm volatile("cp.async.cg.shared.global [%0], [%1], 16;" :: "r"(dst), "l"(src));
}
#define CP_COMMIT() asm volatile("cp.async.commit_group;" ::: "memory")
#define CP_WAIT1()  asm volatile("cp.async.wait_group 1;" ::: "memory")
#define CP_WAIT0()  asm volatile("cp.async.wait_group 0;" ::: "memory")

// ---------------------------------------------------------------------------
// tf32 GEMM, mma.sync + cp.async + ldmatrix.
//   C = (A @ Bt^T + bias?) * scale + shift
// A [M,768] row-major, Bt [N,768] row-major (K contiguous both sides).
// Block tile 128x128, K-chunk 32, 3-stage cp.async pipeline.
// 8 warps 2x4, warp tile 64x32. Operands fed to MMA as raw fp32 (truncated tf32).
// Per-stage smem: A 16KB + B 16KB, XOR-swizzled 128B rows of 8x16B units.
// ---------------------------------------------------------------------------
#define KT       32
#define NCH      (768/KT)      // 24
#define STG_FLT  8192          // floats per stage (A 4096 + B 4096)
#define GEMM_SMEM (3 * STG_FLT * 4)   // 98304

__global__ __launch_bounds__(256, 2)
void gemm_mma(const float* __restrict__ A, const float* __restrict__ Bt,
              float* __restrict__ C, int N,
              const float* __restrict__ bias,
              const float* __restrict__ scale,
              const float* __restrict__ shift)
{
    extern __shared__ float smem[];
    const uint32_t sb = smem_u32(smem);
    const int tid  = threadIdx.x;
    const int lane = tid & 31;
    const int warp = tid >> 5;
    const int g = lane >> 2;
    const int q = lane & 3;
    const int wm0 = (warp >> 2) * 64;
    const int wn0 = (warp & 3) * 32;
    const int m0 = blockIdx.y * 128;
    const int n0 = blockIdx.x * 128;

    float acc[4][4][4];
#pragma unroll
    for (int mf = 0; mf < 4; mf++)
#pragma unroll
        for (int nf = 0; nf < 4; nf++)
#pragma unroll
            for (int cc = 0; cc < 4; cc++) acc[mf][nf][cc] = 0.f;

    // per-thread load indices (4 units A + 4 units B per stage)
    const int r_ld = tid >> 3;        // base row for unit group
    const int u_ld = tid & 7;         // unit within row
    // each iteration advances row by 32 (256 threads / 8 units)

    // frag address bases (lane-dependent parts)
    const int rowA_l = lane & 15;             // + wm0 + mf*16
    const int rowB_l = lane & 7;              // + wn0 + nf*8
    const int selA = lane >> 4;               // 0/1 -> unit +0/+1
    const int selB = lane >> 3;               // 0..3

#define LOAD_STAGE(s, kc) do { \
    uint32_t ab = sb + (s) * (STG_FLT * 4); \
    uint32_t bb = ab + 16384; \
    _Pragma("unroll") \
    for (int i = 0; i < 4; i++) { \
        int r = r_ld + i * 32; \
        uint32_t off = ((uint32_t)(r * 8 + (u_ld ^ (r & 7)))) << 4; \
        cp16(ab + off, A  + (size_t)(m0 + r) * 768 + (kc) * KT + u_ld * 4); \
        cp16(bb + off, Bt + (size_t)(n0 + r) * 768 + (kc) * KT + u_ld * 4); \
    } \
} while (0)

    LOAD_STAGE(0, 0); CP_COMMIT();
    LOAD_STAGE(1, 1); CP_COMMIT();

    for (int kc = 0; kc < NCH; kc++) {
        if (kc >= NCH - 2) { CP_WAIT0(); } else { CP_WAIT1(); }
        __syncthreads();
        if (kc + 2 < NCH) {
            LOAD_STAGE((kc + 2) % 3, kc + 2);
            CP_COMMIT();
        }
        const uint32_t ab = sb + (kc % 3) * (STG_FLT * 4);
        const uint32_t bb = ab + 16384;

#pragma unroll
        for (int ksp = 0; ksp < 2; ksp++) {
            uint32_t bf[4][4];
#pragma unroll
            for (int nf = 0; nf < 4; nf++) {
                int row = wn0 + nf * 8 + rowB_l;
                uint32_t addr = bb + row * 128 +
                                (((4 * ksp + selB) ^ (row & 7)) << 4);
                LDSM_X4(bf[nf][0], bf[nf][1], bf[nf][2], bf[nf][3], addr);
            }
#pragma unroll
            for (int k2 = 0; k2 < 2; k2++) {
                int ks = ksp * 2 + k2;
                uint32_t af[4][4];
#pragma unroll
                for (int mf = 0; mf < 4; mf++) {
                    int row = wm0 + mf * 16 + rowA_l;
                    uint32_t addr = ab + row * 128 +
                                    (((2 * ks + selA) ^ (row & 7)) << 4);
                    LDSM_X4(af[mf][0], af[mf][1], af[mf][2], af[mf][3], addr);
                }
#pragma unroll
                for (int mf = 0; mf < 4; mf++)
#pragma unroll
                    for (int nf = 0; nf < 4; nf++)
                        mma_tf32(acc[mf][nf],
                                 af[mf][0], af[mf][1], af[mf][2], af[mf][3],
                                 bf[nf][2 * k2], bf[nf][2 * k2 + 1]);
            }
        }
        __syncthreads();
    }

    // epilogue: (acc + bias) * scale + shift
#pragma unroll
    for (int nf = 0; nf < 4; nf++) {
        int c = n0 + wn0 + nf * 8 + 2 * q;
        float2 sc = *(const float2*)(scale + c);
        float2 sh = *(const float2*)(shift + c);
        float2 bi = make_float2(0.f, 0.f);
        if (bias) bi = *(const float2*)(bias + c);
#pragma unroll
        for (int mf = 0; mf < 4; mf++) {
            int r = m0 + wm0 + mf * 16 + g;
            float2 lo, hi;
            lo.x = (acc[mf][nf][0] + bi.x) * sc.x + sh.x;
            lo.y = (acc[mf][nf][1] + bi.y) * sc.y + sh.y;
            hi.x = (acc[mf][nf][2] + bi.x) * sc.x + sh.x;
            hi.y = (acc[mf][nf][3] + bi.y) * sc.y + sh.y;
            *(float2*)(C + (size_t)r * N + c) = lo;
            *(float2*)(C + (size_t)(r + 8) * N + c) = hi;
        }
    }
}

// ---------------------------------------------------------------------------
// 32x32 tiled transpose
// ---------------------------------------------------------------------------
__global__ void transpose32(const float* __restrict__ in, float* __restrict__ out,
                            int R, int C)
{
    __shared__ float t[32][33];
    const int c0 = blockIdx.x * 32, r0 = blockIdx.y * 32;
#pragma unroll
    for (int i = 0; i < 32; i += 8)
        t[threadIdx.y + i][threadIdx.x] = in[(size_t)(r0 + threadIdx.y + i) * C + c0 + threadIdx.x];
    __syncthreads();
#pragma unroll
    for (int i = 0; i < 32; i += 8)
        out[(size_t)(c0 + threadIdx.y + i) * R + r0 + threadIdx.x] = t[threadIdx.x][threadIdx.y + i];
}

// ---------------------------------------------------------------------------
// tf32 flash attention, ldmatrix for Q/K fragments.
// grid (SEQ/64, BATCH*NHEADS), 128 threads (4 warps), 16 q-rows per warp.
// ---------------------------------------------------------------------------
#define KS_STRIDE 68
#define VS_STRIDE 72

__global__ __launch_bounds__(128)
void attn_tf32(const float* __restrict__ qkv, float* __restrict__ out)
{
    __shared__ uint32_t Ks[64 * KS_STRIDE];
    __shared__ uint32_t Vs[64 * VS_STRIDE];

    const int tid  = threadIdx.x;
    const int lane = tid & 31;
    const int warp = tid >> 5;
    const int g = lane >> 2;
    const int q = lane & 3;
    const int s0 = blockIdx.x * 64;
    const int bh = blockIdx.y;
    const int b = bh / NHEADS;
    const int h = bh - b * NHEADS;

    const uint32_t ksb = smem_u32(Ks);
    const float* qbase = qkv + (size_t)b * SEQ * QKV_N + h * HDIM;
    const float* kbase = qbase + HID;
    const float* vbase = qbase + 2 * HID;

    // stage Q tile into Ks, extract A-fragments via ldmatrix
#pragma unroll
    for (int it = 0; it < 8; it++) {
        int u = tid + it * 128;
        int r = u >> 4, c4 = u & 15;
        float4 v = *(const float4*)(qbase + (size_t)(s0 + r) * QKV_N + c4 * 4);
        *(uint4*)(&Ks[r * KS_STRIDE + c4 * 4]) = cvt4(v);
    }
    __syncthreads();

    uint32_t qa[8][4];
    {
        int row = warp * 16 + (lane & 15);
        uint32_t base = ksb + row * (KS_STRIDE * 4);
#pragma unroll
        for (int ks = 0; ks < 8; ks++) {
            uint32_t addr = base + (2 * ks + (lane >> 4)) * 16;
            LDSM_X4(qa[ks][0], qa[ks][1], qa[ks][2], qa[ks][3], addr);
        }
    }
    __syncthreads();

    float o_acc[8][4];
#pragma unroll
    for (int nf = 0; nf < 8; nf++)
#pragma unroll
        for (int cc = 0; cc < 4; cc++) o_acc[nf][cc] = 0.f;
    float m0r = -1e30f, m1r = -1e30f, l0r = 0.f, l1r = 0.f;
    const float sm_scale = 0.125f;

    const int src0 = (lane & ~3) | (q >> 1);
    const int src2 = (lane & ~3) | ((q >> 1) + 2);
    const int sel = q & 1;
    const int kfrow_l = lane & 7;
    const int kfsel = lane >> 3;

    for (int t = 0; t < SEQ / 64; t++) {
        const int j0 = t * 64;
#pragma unroll
        for (int it = 0; it < 8; it++) {
            int u = tid + it * 128;
            int r = u >> 4, c4 = u & 15;
            float4 kv = *(const float4*)(kbase + (size_t)(j0 + r) * QKV_N + c4 * 4);
            *(uint4*)(&Ks[r * KS_STRIDE + c4 * 4]) = cvt4(kv);
            float4 vv = *(const float4*)(vbase + (size_t)(j0 + r) * QKV_N + c4 * 4);
            *(uint4*)(&Vs[r * VS_STRIDE + c4 * 4]) = cvt4(vv);
        }
        __syncthreads();

        // S = Q K^T : K B-frags via ldmatrix.x4 (2 k-steps per load)
        float s[8][4];
#pragma unroll
        for (int nf = 0; nf < 8; nf++)
#pragma unroll
            for (int cc = 0; cc < 4; cc++) s[nf][cc] = 0.f;

#pragma unroll
        for (int ksp = 0; ksp < 4; ksp++) {
#pragma unroll
            for (int nh = 0; nh < 2; nh++) {
                uint32_t kb[4][4];
#pragma unroll
                for (int nn = 0; nn < 4; nn++) {
                    int nf = nh * 4 + nn;
                    int row = nf * 8 + kfrow_l;
                    uint32_t addr = ksb + row * (KS_STRIDE * 4) +
                                    (4 * ksp + kfsel) * 16;
                    LDSM_X4(kb[nn][0], kb[nn][1], kb[nn][2], kb[nn][3], addr);
                }
#pragma unroll
                for (int k2 = 0; k2 < 2; k2++) {
                    int ks = ksp * 2 + k2;
#pragma unroll
                    for (int nn = 0; nn < 4; nn++)
                        mma_tf32(s[nh * 4 + nn],
                                 qa[ks][0], qa[ks][1], qa[ks][2], qa[ks][3],
                                 kb[nn][2 * k2], kb[nn][2 * k2 + 1]);
                }
            }
        }

        // online softmax
        float mx0 = -1e30f, mx1 = -1e30f;
#pragma unroll
        for (int nf = 0; nf < 8; nf++) {
#pragma unroll
            for (int cc = 0; cc < 4; cc++) s[nf][cc] *= sm_scale;
            mx0 = fmaxf(mx0, fmaxf(s[nf][0], s[nf][1]));
            mx1 = fmaxf(mx1, fmaxf(s[nf][2], s[nf][3]));
        }
        mx0 = fmaxf(mx0, __shfl_xor_sync(0xffffffffu, mx0, 1));
        mx0 = fmaxf(mx0, __shfl_xor_sync(0xffffffffu, mx0, 2));
        mx1 = fmaxf(mx1, __shfl_xor_sync(0xffffffffu, mx1, 1));
        mx1 = fmaxf(mx1, __shfl_xor_sync(0xffffffffu, mx1, 2));
        float nm0 = fmaxf(m0r, mx0);
        float nm1 = fmaxf(m1r, mx1);
        float sum0 = 0.f, sum1 = 0.f;
#pragma unroll
        for (int nf = 0; nf < 8; nf++) {
            s[nf][0] = __expf(s[nf][0] - nm0);
            s[nf][1] = __expf(s[nf][1] - nm0);
            s[nf][2] = __expf(s[nf][2] - nm1);
            s[nf][3] = __expf(s[nf][3] - nm1);
            sum0 += s[nf][0] + s[nf][1];
            sum1 += s[nf][2] + s[nf][3];
        }
        sum0 += __shfl_xor_sync(0xffffffffu, sum0, 1);
        sum0 += __shfl_xor_sync(0xffffffffu, sum0, 2);
        sum1 += __shfl_xor_sync(0xffffffffu, sum1, 1);
        sum1 += __shfl_xor_sync(0xffffffffu, sum1, 2);
        float corr0 = __expf(m0r - nm0);
        float corr1 = __expf(m1r - nm1);
        l0r = l0r * corr0 + sum0;
        l1r = l1r * corr1 + sum1;
        m0r = nm0; m1r = nm1;
#pragma unroll
        for (int nf = 0; nf < 8; nf++) {
            o_acc[nf][0] *= corr0; o_acc[nf][1] *= corr0;
            o_acc[nf][2] *= corr1; o_acc[nf][3] *= corr1;
        }

        // P C-layout -> A-layout via shuffles; O += P @ V (V scalar loads)
#pragma unroll
        for (int ks = 0; ks < 8; ks++) {
            float v00 = __shfl_sync(0xffffffffu, s[ks][0], src0);
            float v01 = __shfl_sync(0xffffffffu, s[ks][1], src0);
            float v20 = __shfl_sync(0xffffffffu, s[ks][0], src2);
            float v21 = __shfl_sync(0xffffffffu, s[ks][1], src2);
            float v10 = __shfl_sync(0xffffffffu, s[ks][2], src0);
            float v11 = __shfl_sync(0xffffffffu, s[ks][3], src0);
            float v30 = __shfl_sync(0xffffffffu, s[ks][2], src2);
            float v31 = __shfl_sync(0xffffffffu, s[ks][3], src2);
            uint32_t pa0 = f2tf32(sel ? v01 : v00);
            uint32_t pa1 = f2tf32(sel ? v11 : v10);
            uint32_t pa2 = f2tf32(sel ? v21 : v20);
            uint32_t pa3 = f2tf32(sel ? v31 : v30);
#pragma unroll
            for (int nf = 0; nf < 8; nf++) {
                uint32_t b0 = Vs[(ks * 8 + q) * VS_STRIDE + nf * 8 + g];
                uint32_t b1 = Vs[(ks * 8 + q + 4) * VS_STRIDE + nf * 8 + g];
                mma_tf32(o_acc[nf], pa0, pa1, pa2, pa3, b0, b1);
            }
        }
        __syncthreads();
    }

    float inv0 = 1.0f / l0r;
    float inv1 = 1.0f / l1r;
    int r0 = b * SEQ + s0 + warp * 16 + g;
#pragma unroll
    for (int nf = 0; nf < 8; nf++) {
        int c = h * HDIM + nf * 8 + 2 * q;
        float2 lo, hi;
        lo.x = o_acc[nf][0] * inv0; lo.y = o_acc[nf][1] * inv0;
        hi.x = o_acc[nf][2] * inv1; hi.y = o_acc[nf][3] * inv1;
        *(float2*)(out + (size_t)r0 * HID + c) = lo;
        *(float2*)(out + (size_t)(r0 + 8) * HID + c) = hi;
    }
}

// ---------------------------------------------------------------------------
extern "C" void kernel_launch(void* const* d_in, const int* in_sizes, int n_in,
                              void* d_out, int out_size)
{
    (void)in_sizes; (void)n_in; (void)out_size;
    const float* x      = (const float*)d_in[0];
    const float* Wqkv   = (const float*)d_in[1];
    const float* scale1 = (const float*)d_in[2];
    const float* shift1 = (const float*)d_in[3];
    const float* Wout   = (const float*)d_in[4];
    const float* bout   = (const float*)d_in[5];
    const float* scale2 = (const float*)d_in[6];
    const float* shift2 = (const float*)d_in[7];
    float* out = (float*)d_out;

    float *qkv_buf = nullptr, *o_buf = nullptr, *wt_qkv = nullptr, *wt_out = nullptr;
    cudaGetSymbolAddress((void**)&qkv_buf, g_qkv);
    cudaGetSymbolAddress((void**)&o_buf, g_o);
    cudaGetSymbolAddress((void**)&wt_qkv, g_wt_qkv);
    cudaGetSymbolAddress((void**)&wt_out, g_wt_out);

    static bool attr_set = false;
    if (!attr_set) {
        cudaFuncSetAttribute(gemm_mma, cudaFuncAttributeMaxDynamicSharedMemorySize, GEMM_SMEM);
        attr_set = true;
    }

    // 0) weight transposes -> K-contiguous Bt layouts
    {
        dim3 blk(32, 8);
        transpose32<<<dim3(QKV_N / 32, HID / 32), blk>>>(Wqkv, wt_qkv, HID, QKV_N);
        transpose32<<<dim3(HID / 32, HID / 32), blk>>>(Wout, wt_out, HID, HID);
    }
    // 1) QKV projection + SSF affine
    gemm_mma<<<dim3(QKV_N / 128, MTOT / 128), 256, GEMM_SMEM>>>(
        x, wt_qkv, qkv_buf, QKV_N, nullptr, scale1, shift1);
    // 2) attention
    attn_tf32<<<dim3(SEQ / 64, BATCH * NHEADS), 128>>>(qkv_buf, o_buf);
    // 3) out projection + bias + SSF affine
    gemm_mma<<<dim3(HID / 128, MTOT / 128), 256, GEMM_SMEM>>>(
        o_buf, wt_out, out, HID, bout, scale2, shift2);
}